// round 17
// baseline (speedup 1.0000x reference)
#include <cuda_runtime.h>
#include <cstdint>
#include <math.h>

// ============================================================================
// Problem constants
// ============================================================================
#define N_ROWS   30000
#define D_IN     784
#define N_CLS    10
#define NC       100
#define MAXK     12
#define INITB    4000
#define BINC     2166
#define NBUCK    4096
#define WSZ      (D_IN * NC)       // 78400 W elements per iteration
#define BM       64
#define KT       56
#define NTILE    (D_IN / KT)       // 14
#define GRID     435               // = ceil(27826/64); <= 148*3 resident
#define HC_WARPS 12
#define HC_STRIDE (GRID * HC_WARPS)  // 5220 warps

// ============================================================================
// Device globals
// ============================================================================
__device__ uint2 dk_wA[MAXK], dk_bA[MAXK];
__device__ uint2 dk_skA[MAXK][2];

__device__ unsigned long long d_packA[MAXK * N_ROWS];
__device__ unsigned long long d_pack2A[MAXK * N_ROWS];
__device__ unsigned int d_histA[MAXK * NBUCK];   // static zero-init; self-zeroed
__device__ unsigned int d_offsA[MAXK * NBUCK];
__device__ unsigned int d_woffsA[MAXK * NBUCK];
__device__ int d_permA[MAXK * N_ROWS];

__device__ float d_Wr[MAXK * WSZ];               // row-major  [d][c]
__device__ float d_WrT[MAXK * NC * D_IN];        // col-major  [c][d]
__device__ float d_br[MAXK * NC];
__device__ float d_H[N_ROWS * MAXK];
__device__ float d_part[436 * 1104];
__device__ int   d_best;
__device__ double d_gpart[125 * 32];
__device__ double d_G[144];                      // persistent, incremental
__device__ double d_C[120];
__device__ float d_beta[MAXK * N_CLS];
__device__ int d_ctr1;
__device__ int d_ctr2;
__device__ unsigned int g_sync;                  // monotonic grid-sync counter

// ============================================================================
// JAX Threefry-2x32 (partitionable variant, bit-exact)
// ============================================================================
__device__ __forceinline__ uint32_t rotl32(uint32_t x, int r) {
    return (x << r) | (x >> (32 - r));
}

__device__ __forceinline__ void tf2x32(uint32_t k0, uint32_t k1,
                                       uint32_t x0, uint32_t x1,
                                       uint32_t& o0, uint32_t& o1) {
    uint32_t ks2 = k0 ^ k1 ^ 0x1BD11BDAu;
    x0 += k0; x1 += k1;
#define TFR(r) { x0 += x1; x1 = rotl32(x1, r); x1 ^= x0; }
    TFR(13) TFR(15) TFR(26) TFR(6)   x0 += k1;  x1 += ks2 + 1u;
    TFR(17) TFR(29) TFR(16) TFR(24)  x0 += ks2; x1 += k0  + 2u;
    TFR(13) TFR(15) TFR(26) TFR(6)   x0 += k0;  x1 += k1  + 3u;
    TFR(17) TFR(29) TFR(16) TFR(24)  x0 += k1;  x1 += ks2 + 4u;
    TFR(13) TFR(15) TFR(26) TFR(6)   x0 += ks2; x1 += k0  + 5u;
#undef TFR
    o0 = x0; o1 = x1;
}

__device__ __forceinline__ uint32_t rbits(uint2 key, uint32_t i) {
    uint32_t o0, o1;
    tf2x32(key.x, key.y, 0u, i, o0, o1);
    return o0 ^ o1;
}

__device__ __forceinline__ uint2 subkey(uint2 key, uint32_t j) {
    uint2 r;
    tf2x32(key.x, key.y, 0u, j, r.x, r.y);
    return r;
}

__device__ __forceinline__ float uni01(uint32_t bits) {
    return __uint_as_float((bits >> 9) | 0x3f800000u) - 1.0f;
}

// ============================================================================
// Grid-wide sync: monotonic counter, all GRID blocks co-resident by design.
// ============================================================================
__device__ __forceinline__ void gsync() {
    __syncthreads();
    if (threadIdx.x == 0) {
        __threadfence();
        unsigned int my = atomicAdd(&g_sync, 1u);
        unsigned int target = (my / (unsigned)GRID + 1u) * (unsigned)GRID;
        while (*((volatile unsigned int*)&g_sync) < target) __nanosleep(64);
    }
    __syncthreads();
}

// ============================================================================
// Setup: key chain + all W/b (row-major AND transposed)
// ============================================================================
__global__ void k_init() {
    if (threadIdx.x != 0) return;
    uint2 key = make_uint2(0u, 42u);           // jax.random.key(42)
    for (int k = 0; k < MAXK; k++) {
        uint2 nk    = subkey(key, 0);
        uint2 kperm = subkey(key, 1);
        dk_wA[k]    = subkey(key, 2);
        dk_bA[k]    = subkey(key, 3);
        key = nk;
        uint2 kp1    = subkey(kperm, 0);
        dk_skA[k][0] = subkey(kperm, 1);
        dk_skA[k][1] = subkey(kp1,   1);
    }
}

__global__ void k_genc_all() {
    int e = blockIdx.x * blockDim.x + threadIdx.x;
    if (e >= MAXK * (WSZ + NC)) return;
    int k = e / (WSZ + NC);
    int j = e % (WSZ + NC);
    if (j < WSZ) {
        float u = uni01(rbits(dk_wA[k], (uint32_t)j));
        int col = j % NC, row = j / NC;
        float lam = (col < 50) ? 1.0f : 10.0f;
        float val = lam * (2.0f * u - 1.0f);
        d_Wr[k * WSZ + j] = val;
        d_WrT[(k * NC + col) * D_IN + row] = val;
    } else {
        int jj = j - WSZ;
        float u = uni01(rbits(dk_bA[k], (uint32_t)jj));
        float lam = (jj < 50) ? 1.0f : 10.0f;
        d_br[k * NC + jj] = lam * (2.0f * u - 1.0f);
    }
}

// ============================================================================
// Batched permutation pipeline (all 12 iterations per launch)
// ============================================================================
__global__ void k_genhist_all(int round) {
    int i = blockIdx.x * blockDim.x + threadIdx.x;
    int it = blockIdx.y;
    if (i >= N_ROWS) return;
    uint32_t key = rbits(dk_skA[it][round], (uint32_t)i);
    uint32_t val = (round == 0) ? (uint32_t)i : (uint32_t)d_permA[it * N_ROWS + i];
    unsigned long long p = ((unsigned long long)key << 30) |
                           ((unsigned long long)(uint32_t)i << 15) |
                           (unsigned long long)val;
    d_packA[it * N_ROWS + i] = p;
    atomicAdd(&d_histA[it * NBUCK + (key >> 20)], 1u);
}

__global__ void k_scan_all() {
    __shared__ unsigned int wsum[32];
    int it = blockIdx.x;
    int t = threadIdx.x;
    const unsigned int* hist = d_histA + it * NBUCK;
    unsigned int h0[4], s = 0;
#pragma unroll
    for (int j = 0; j < 4; j++) { h0[j] = hist[t * 4 + j]; s += h0[j]; }
    int lane = t & 31, wid = t >> 5;
    unsigned int v = s;
#pragma unroll
    for (int o = 1; o < 32; o <<= 1) {
        unsigned int u = __shfl_up_sync(0xffffffffu, v, o);
        if (lane >= o) v += u;
    }
    if (lane == 31) wsum[wid] = v;
    __syncthreads();
    if (wid == 0) {
        unsigned int w = wsum[lane];
#pragma unroll
        for (int o = 1; o < 32; o <<= 1) {
            unsigned int u = __shfl_up_sync(0xffffffffu, w, o);
            if (lane >= o) w += u;
        }
        wsum[lane] = w;
    }
    __syncthreads();
    unsigned int base = v - s + (wid > 0 ? wsum[wid - 1] : 0u);
#pragma unroll
    for (int j = 0; j < 4; j++) {
        d_offsA[it * NBUCK + t * 4 + j]  = base;
        d_woffsA[it * NBUCK + t * 4 + j] = base;
        base += h0[j];
    }
}

__global__ void k_scatter_all() {
    int i = blockIdx.x * blockDim.x + threadIdx.x;
    int it = blockIdx.y;
    if (i >= N_ROWS) return;
    unsigned long long p = d_packA[it * N_ROWS + i];
    unsigned int b = (unsigned int)(p >> 50);
    unsigned int pos = atomicAdd(&d_woffsA[it * NBUCK + b], 1u);
    d_pack2A[it * N_ROWS + pos] = p;
}

__global__ void k_bsort_all() {
    int g = blockIdx.x * blockDim.x + threadIdx.x;
    if (g >= MAXK * NBUCK) return;
    int it = g / NBUCK;
    unsigned int start = d_offsA[g];
    unsigned int cnt = d_histA[g];
    if (cnt > 64u) cnt = 64u;
    unsigned long long a[64];
    const unsigned long long* src = d_pack2A + it * N_ROWS;
    for (unsigned int i = 0; i < cnt; i++) a[i] = src[start + i];
    for (unsigned int i = 1; i < cnt; i++) {
        unsigned long long key = a[i];
        int j = (int)i - 1;
        while (j >= 0 && a[j] > key) { a[j + 1] = a[j]; j--; }
        a[j + 1] = key;
    }
    int* dst = d_permA + it * N_ROWS;
    for (unsigned int i = 0; i < cnt; i++)
        dst[start + i] = (int)(a[i] & 0x7FFFull);
    d_histA[g] = 0u;
}

// ============================================================================
// Persistent main kernel: all 12 iterations, 3 grid-syncs per iteration.
// Phase A: cand GEMM + partial scores (blocks < nb) + last-arriver vred.
// Phase C: h_c over all rows (warp-per-row, all blocks) + W/b output.
// Phase D: incremental Gram partials (blocks < 125) + last-arriver solve.
// Cross-block data (d_H, d_beta, d_best, d_part, d_gpart, d_G, d_C) is read
// via __ldcg/volatile: L1 persists within a launch, only L2 is coherent.
// ============================================================================
#define SBUF_BYTES (KT * 68 * 4 + KT * NC * 4)   // 15232 + 22400 = 37632

__global__ void __launch_bounds__(400, 3)
k_main(const float* __restrict__ X, const float* __restrict__ Y,
       float* __restrict__ out) {
    __shared__ __align__(16) char sraw[SBUF_BYTES];
    __shared__ float ekS[BM][N_CLS];
    __shared__ float betaS[MAXK * N_CLS];
    __shared__ int idxS[BM];
    __shared__ int sflag;
    __shared__ float vS[NC];
    __shared__ float s_b;

    float (*As)[68] = reinterpret_cast<float(*)[68]>(sraw);
    float (*Bs)[NC] = reinterpret_cast<float(*)[NC]>(sraw + KT * 68 * 4);
    float* Wc  = reinterpret_cast<float*>(sraw);              // phase C
    double* Ls = reinterpret_cast<double*>(sraw);             // phase D [12*12]
    double* Cs = reinterpret_cast<double*>(sraw + 144 * 8);   // phase D [12*10]

    int tid = threadIdx.x;
    int b = blockIdx.x;
    int lane = tid & 31;

    int batch = INITB;
    for (int kit = 0; kit < MAXK; kit++) {
        int n = kit;
        int nb = (batch + BM - 1) / BM;

        // ================= Phase A: candidate evaluation =================
        if (b < nb) {
            int tx = tid >> 4;             // candidate group (4 cands)
            int ty = tid & 15;             // row group (4 rows)
            int row0 = b * BM;
            const float* Wit = d_Wr + kit * WSZ;
            const int* perm = d_permA + kit * N_ROWS;

            if (tid < BM) {
                int g = row0 + tid;
                idxS[tid] = (g < batch) ? perm[g] : -1;
            }
            if (tid >= 64 && tid < 64 + n * N_CLS)
                betaS[tid - 64] = __ldcg(&d_beta[tid - 64]);
            __syncthreads();
            for (int t = tid; t < BM * N_CLS; t += 400) {
                int r = t / N_CLS, j = t % N_CLS;
                int idx = idxS[r];
                float e = 0.0f;
                if (idx >= 0) {
                    float yv = 0.0f;
                    const float* hr = d_H + (size_t)idx * MAXK;
                    for (int q = 0; q < n; q++)
                        yv += __ldcg(&hr[q]) * betaS[q * N_CLS + j];
                    e = Y[idx * N_CLS + j] - yv;
                }
                ekS[r][j] = e;
            }

            float acc[16];
#pragma unroll
            for (int i = 0; i < 16; i++) acc[i] = 0.0f;

            for (int t14 = 0; t14 < NTILE; t14++) {
                int k0 = t14 * KT;
                __syncthreads();
                for (int e = tid; e < BM * (KT / 4); e += 400) {
                    int r = e / (KT / 4);
                    int v = e % (KT / 4);
                    int idx = idxS[r];
                    float4 x = make_float4(0.f, 0.f, 0.f, 0.f);
                    if (idx >= 0)
                        x = *reinterpret_cast<const float4*>(X + (size_t)idx * D_IN + k0 + v * 4);
                    As[v * 4 + 0][r] = x.x;
                    As[v * 4 + 1][r] = x.y;
                    As[v * 4 + 2][r] = x.z;
                    As[v * 4 + 3][r] = x.w;
                }
                {
                    const float4* src = reinterpret_cast<const float4*>(Wit + k0 * NC);
                    float4* dst = reinterpret_cast<float4*>(&Bs[0][0]);
                    for (int e = tid; e < KT * NC / 4; e += 400) dst[e] = src[e];
                }
                __syncthreads();
#pragma unroll 8
                for (int q = 0; q < KT; q++) {
                    float4 a = *reinterpret_cast<const float4*>(&As[q][ty * 4]);
                    float4 bb = *reinterpret_cast<const float4*>(&Bs[q][tx * 4]);
                    acc[0]  += a.x * bb.x;  acc[1]  += a.x * bb.y;
                    acc[2]  += a.x * bb.z;  acc[3]  += a.x * bb.w;
                    acc[4]  += a.y * bb.x;  acc[5]  += a.y * bb.y;
                    acc[6]  += a.y * bb.z;  acc[7]  += a.y * bb.w;
                    acc[8]  += a.z * bb.x;  acc[9]  += a.z * bb.y;
                    acc[10] += a.z * bb.z;  acc[11] += a.z * bb.w;
                    acc[12] += a.w * bb.x;  acc[13] += a.w * bb.y;
                    acc[14] += a.w * bb.z;  acc[15] += a.w * bb.w;
                }
            }

            const float* bit = d_br + kit * NC;
            float bj[4];
#pragma unroll
            for (int j = 0; j < 4; j++) bj[j] = bit[tx * 4 + j];
            bool vld[4];
#pragma unroll
            for (int i = 0; i < 4; i++) vld[i] = (idxS[ty * 4 + i] >= 0);

            float h[16];
#pragma unroll
            for (int i = 0; i < 4; i++)
#pragma unroll
                for (int j = 0; j < 4; j++) {
                    float z = acc[i * 4 + j] + bj[j];
                    h[i * 4 + j] = vld[i] ? (1.0f / (1.0f + expf(-z))) : 0.0f;
                }

            unsigned int msk = 0xFFFFu << (lane & 16);
            int pbase = b * 1104 + (tx * 4) * 11;

#pragma unroll
            for (int j = 0; j < 4; j++) {
                float s2 = h[j] * h[j] + h[4 + j] * h[4 + j] +
                           h[8 + j] * h[8 + j] + h[12 + j] * h[12 + j];
#pragma unroll
                for (int o = 1; o < 16; o <<= 1) s2 += __shfl_xor_sync(msk, s2, o);
                if (ty == 0) d_part[pbase + j * 11 + 10] = s2;
            }
#pragma unroll
            for (int jc = 0; jc < N_CLS; jc++) {
                float e0 = ekS[ty * 4 + 0][jc];
                float e1v = ekS[ty * 4 + 1][jc];
                float e2 = ekS[ty * 4 + 2][jc];
                float e3 = ekS[ty * 4 + 3][jc];
#pragma unroll
                for (int j = 0; j < 4; j++) {
                    float m = e0 * h[j] + e1v * h[4 + j] + e2 * h[8 + j] + e3 * h[12 + j];
#pragma unroll
                    for (int o = 1; o < 16; o <<= 1) m += __shfl_xor_sync(msk, m, o);
                    if (ty == 0) d_part[pbase + j * 11 + jc] = m;
                }
            }

            // last-arriver vred + argmax
            __syncthreads();
            if (tid == 0) {
                __threadfence();
                int o = atomicAdd(&d_ctr1, 1);
                sflag = (o == nb - 1) ? 1 : 0;
            }
            __syncthreads();
            if (sflag) {
                __threadfence();
                int c = tid >> 2, p = tid & 3;
                double m[N_CLS];
                double s2 = 0.0;
                for (int j = 0; j < N_CLS; j++) m[j] = 0.0;
                for (int b2 = p; b2 < nb; b2 += 4) {
                    const float* pp = &d_part[b2 * 1104 + c * 11];
                    for (int j = 0; j < N_CLS; j++) m[j] += (double)__ldcg(&pp[j]);
                    s2 += (double)__ldcg(&pp[10]);
                }
                unsigned int m4 = 0xFu << (lane & ~3);
                for (int j = 0; j < N_CLS; j++) {
                    m[j] += __shfl_xor_sync(m4, m[j], 1);
                    m[j] += __shfl_xor_sync(m4, m[j], 2);
                }
                s2 += __shfl_xor_sync(m4, s2, 1);
                s2 += __shfl_xor_sync(m4, s2, 2);
                if (p == 0) {
                    double num = 0.0;
                    for (int j = 0; j < N_CLS; j++) num += m[j] * m[j];
                    vS[c] = (float)(num / (10.0 * s2));
                }
                __syncthreads();
                if (tid == 0) {
                    float best = -1.0f;
                    int bi = 0;
                    for (int i = 0; i < NC; i++)
                        if (vS[i] > best) { best = vS[i]; bi = i; }
                    d_best = bi;
                    d_ctr1 = 0;
                }
            }
        }
        gsync();   // publishes d_best (+ frees As/Bs smem)

        // ================= Phase C: h_c over all rows =================
        {
            int best = *((volatile int*)&d_best);
            const float* wt = d_WrT + (size_t)(kit * NC + best) * D_IN;
            for (int t = tid; t < D_IN; t += 400) Wc[t] = wt[t];
            if (tid == 0) s_b = d_br[kit * NC + best];
            __syncthreads();
            int w = tid >> 5;
            if (w < HC_WARPS) {
                for (int row = b * HC_WARPS + w; row < N_ROWS; row += HC_STRIDE) {
                    const float* xr = X + (size_t)row * D_IN;
                    float s = 0.0f;
                    for (int q = lane; q < D_IN; q += 32) s += xr[q] * Wc[q];
#pragma unroll
                    for (int o = 16; o; o >>= 1) s += __shfl_down_sync(0xffffffffu, s, o);
                    if (lane == 0) {
                        float hv = 1.0f / (1.0f + expf(-(s + s_b)));
                        d_H[row * MAXK + kit] = hv;
                    }
                }
            }
            if (b == 0) {
                for (int t = tid; t < D_IN; t += 400) out[t * MAXK + kit] = Wc[t];
                if (tid == 0) out[D_IN * MAXK + kit] = s_b;
            }
        }
        gsync();   // publishes d_H column kit

        // ================= Phase D: Gram + solve =================
        if (b < 125) {
            int entry = tid >> 3, s = tid & 7;
            int nn = kit + 1;
            int nent = nn + N_CLS;
            double acc = 0.0;
            int r0 = b * 240;
            if (entry < nent) {
                if (entry < nn) {
                    for (int i = 0; i < 30; i++) {
                        int r = r0 + s + 8 * i;
                        double hk = (double)__ldcg(&d_H[r * MAXK + kit]);
                        acc += hk * (double)__ldcg(&d_H[r * MAXK + entry]);
                    }
                } else {
                    int cls = entry - nn;
                    for (int i = 0; i < 30; i++) {
                        int r = r0 + s + 8 * i;
                        double hk = (double)__ldcg(&d_H[r * MAXK + kit]);
                        acc += hk * (double)Y[r * N_CLS + cls];
                    }
                }
            }
            unsigned int m8 = 0xFFu << (lane & ~7);
            acc += __shfl_xor_sync(m8, acc, 1);
            acc += __shfl_xor_sync(m8, acc, 2);
            acc += __shfl_xor_sync(m8, acc, 4);
            if (s == 0 && entry < 32) d_gpart[b * 32 + entry] = acc;

            __syncthreads();
            if (tid == 0) {
                __threadfence();
                int o = atomicAdd(&d_ctr2, 1);
                sflag = (o == 125 - 1) ? 1 : 0;
            }
            __syncthreads();
            if (sflag) {
                __threadfence();
                int t = tid;
                if (t < 32 && t < nent) {
                    double a0 = 0, a1 = 0, a2 = 0, a3 = 0, a4 = 0;
                    for (int b2 = 0; b2 + 5 <= 125; b2 += 5) {
                        a0 += __ldcg(&d_gpart[(b2 + 0) * 32 + t]);
                        a1 += __ldcg(&d_gpart[(b2 + 1) * 32 + t]);
                        a2 += __ldcg(&d_gpart[(b2 + 2) * 32 + t]);
                        a3 += __ldcg(&d_gpart[(b2 + 3) * 32 + t]);
                        a4 += __ldcg(&d_gpart[(b2 + 4) * 32 + t]);
                    }
                    double sum = ((a0 + a1) + (a2 + a3)) + a4;
                    if (t < nn) {
                        d_G[(nn - 1) * 12 + t] = sum;
                        d_G[t * 12 + (nn - 1)] = sum;
                    } else {
                        d_C[(nn - 1) * 10 + (t - nn)] = sum;
                    }
                }
                __syncthreads();
                for (int e = t; e < nn * nn; e += 400)
                    Ls[(e / nn) * 12 + (e % nn)] = __ldcg(&d_G[(e / nn) * 12 + (e % nn)]);
                for (int e = t; e < nn * 10; e += 400)
                    Cs[e] = __ldcg(&d_C[e]);
                __syncthreads();
                if (t < 32) {
                    for (int j = 0; j < nn; j++) {
                        if (t == 0) {
                            double v = Ls[j * 12 + j];
                            for (int p = 0; p < j; p++) v -= Ls[j * 12 + p] * Ls[j * 12 + p];
                            Ls[j * 12 + j] = sqrt(v);
                        }
                        __syncwarp();
                        if (t > j && t < nn) {
                            double v = Ls[t * 12 + j];
                            for (int p = 0; p < j; p++) v -= Ls[t * 12 + p] * Ls[j * 12 + p];
                            Ls[t * 12 + j] = v / Ls[j * 12 + j];
                        }
                        __syncwarp();
                    }
                }
                __syncthreads();
                if (t < N_CLS) {
                    double z[12];
                    for (int i = 0; i < nn; i++) {
                        double v = Cs[i * 10 + t];
                        for (int p = 0; p < i; p++) v -= Ls[i * 12 + p] * z[p];
                        z[i] = v / Ls[i * 12 + i];
                    }
                    for (int i = nn - 1; i >= 0; i--) {
                        double v = z[i];
                        for (int p = i + 1; p < nn; p++) v -= Ls[p * 12 + i] * z[p];
                        z[i] = v / Ls[i * 12 + i];
                    }
                    for (int i = 0; i < nn; i++) {
                        d_beta[i * 10 + t] = (float)z[i];
                        if (nn == MAXK) out[D_IN * MAXK + MAXK + i * 10 + t] = (float)z[i];
                    }
                }
                if (t == 0) d_ctr2 = 0;
            }
        }
        gsync();   // publishes d_beta for next iteration

        batch += BINC;
    }
}

// ============================================================================
// Launch — 11 graph nodes total
// ============================================================================
extern "C" void kernel_launch(void* const* d_in, const int* in_sizes, int n_in,
                              void* d_out, int out_size) {
    const float* X = (const float*)d_in[0];
    const float* Y = (const float*)d_in[1];
    float* out = (float*)d_out;

    k_init<<<1, 32>>>();
    k_genc_all<<<(MAXK * (WSZ + NC) + 255) / 256, 256>>>();

    dim3 sg((N_ROWS + 255) / 256, MAXK);
    for (int r = 0; r < 2; r++) {
        k_genhist_all<<<sg, 256>>>(r);
        k_scan_all<<<MAXK, 1024>>>();
        k_scatter_all<<<sg, 256>>>();
        k_bsort_all<<<(MAXK * NBUCK + 127) / 128, 128>>>();
    }

    k_main<<<GRID, 400>>>(X, Y, out);
}